// round 9
// baseline (speedup 1.0000x reference)
#include <cuda_runtime.h>
#include <cstdint>

#define NB 32
#define TT 2048
#define II 512
#define HH 1024

// =====================================================================
// Phase 1: proj = x @ w_ih^T + b_ih  -> written into out2 (second half
// of d_out, used as scratch until the final duplicate copy).
// C[M=65536, 1024] = X[65536, 512] @ Wih[1024,512]^T + b
// Tiles: BM=128, BN=64, BK=16, 256 threads, 8x4 micro-tile per thread.
// =====================================================================
__global__ __launch_bounds__(256) void proj_gemm(
    const float* __restrict__ x,
    const float* __restrict__ wih,
    const float* __restrict__ bih,
    float* __restrict__ proj)
{
    __shared__ float As[16][132];   // [k][m], padded
    __shared__ float Bs[16][68];    // [k][n], padded

    const int tid = threadIdx.x;
    const int n0 = blockIdx.x * 64;
    const int m0 = blockIdx.y * 128;

    const int ar = tid >> 2;            // 0..63
    const int ac = (tid & 3) << 2;      // 0,4,8,12
    const int ty = tid >> 4;            // 0..15  (m groups of 8)
    const int tx = tid & 15;            // 0..15  (n groups of 4)

    float acc[8][4];
#pragma unroll
    for (int i = 0; i < 8; i++)
#pragma unroll
        for (int j = 0; j < 4; j++) acc[i][j] = 0.0f;

    for (int kk = 0; kk < II / 16; kk++) {
        const int k0 = kk * 16;
        const float4 a0 = *reinterpret_cast<const float4*>(
            &x[(size_t)(m0 + ar) * II + k0 + ac]);
        const float4 a1 = *reinterpret_cast<const float4*>(
            &x[(size_t)(m0 + 64 + ar) * II + k0 + ac]);
        const float4 b0 = *reinterpret_cast<const float4*>(
            &wih[(size_t)(n0 + ar) * II + k0 + ac]);

        __syncthreads();
        As[ac + 0][ar] = a0.x;  As[ac + 1][ar] = a0.y;
        As[ac + 2][ar] = a0.z;  As[ac + 3][ar] = a0.w;
        As[ac + 0][64 + ar] = a1.x;  As[ac + 1][64 + ar] = a1.y;
        As[ac + 2][64 + ar] = a1.z;  As[ac + 3][64 + ar] = a1.w;
        Bs[ac + 0][ar] = b0.x;  Bs[ac + 1][ar] = b0.y;
        Bs[ac + 2][ar] = b0.z;  Bs[ac + 3][ar] = b0.w;
        __syncthreads();

#pragma unroll
        for (int k = 0; k < 16; k++) {
            const float4 av0 = *reinterpret_cast<const float4*>(&As[k][ty * 8]);
            const float4 av1 = *reinterpret_cast<const float4*>(&As[k][ty * 8 + 4]);
            const float4 bv  = *reinterpret_cast<const float4*>(&Bs[k][tx * 4]);
            float a[8] = {av0.x, av0.y, av0.z, av0.w, av1.x, av1.y, av1.z, av1.w};
            float b[4] = {bv.x, bv.y, bv.z, bv.w};
#pragma unroll
            for (int i = 0; i < 8; i++)
#pragma unroll
                for (int j = 0; j < 4; j++)
                    acc[i][j] += a[i] * b[j];
        }
    }

    const float4 bias = *reinterpret_cast<const float4*>(&bih[n0 + tx * 4]);
#pragma unroll
    for (int r = 0; r < 8; r++) {
        const int m = m0 + ty * 8 + r;
        float4 o;
        o.x = acc[r][0] + bias.x;
        o.y = acc[r][1] + bias.y;
        o.z = acc[r][2] + bias.z;
        o.w = acc[r][3] + bias.w;
        *reinterpret_cast<float4*>(&proj[(size_t)m * HH + n0 + tx * 4]) = o;
    }
}

// =====================================================================
// Phase 2: persistent recurrence (reference semantics!):
//   h_0 = proj[:, 0]
//   h_t = h_{t-1} @ W^T + proj[:, t-1]     for t = 1..T-1   <-- t-1 !!
// h lives in `out` (first half), proj in `out2` (read-only here).
// 128 CTAs x 256 threads. CTA c owns output columns [8c, 8c+8).
// All h (`out`) accesses are .cg (L2-scoped): L1 is not coherent
// across SMs inside a persistent kernel. proj reads may use L1.
// =====================================================================
#define RBLOCKS 128

__device__ unsigned g_count = 0;
__device__ unsigned g_phase = 0;

__device__ __forceinline__ void grid_barrier(int tid)
{
    __syncthreads();
    if (tid == 0) {
        volatile unsigned* vphase = &g_phase;
        const unsigned my = *vphase;      // read BEFORE arriving
        __threadfence();                  // publish out[] writes (L2)
        const unsigned arrived = atomicAdd(&g_count, 1u);
        if (arrived == RBLOCKS - 1) {
            g_count = 0;
            __threadfence();
            *vphase = my + 1;             // release
        } else {
            while (*vphase == my) { }
            __threadfence();              // acquire
        }
    }
    __syncthreads();
}

__global__ __launch_bounds__(256) void recurrence(
    const float* __restrict__ whh,
    const float* __restrict__ proj,
    float* out)
{
    __shared__ float partial[4][32][8];

    const int tid  = threadIdx.x;
    const int w    = tid >> 5;
    const int lane = tid & 31;
    const int jq   = w & 1;        // which 4-column group
    const int ks   = w >> 1;       // which 256-wide k slice (0..3)
    const int j0   = blockIdx.x * 8;

    // Load W slice into registers: Wr[jj][i]
    float Wr[4][8];
#pragma unroll
    for (int jj = 0; jj < 4; jj++) {
        const int j = j0 + jq * 4 + jj;
        const float4 v0 = *reinterpret_cast<const float4*>(
            &whh[(size_t)j * HH + ks * 256 + lane * 4]);
        const float4 v1 = *reinterpret_cast<const float4*>(
            &whh[(size_t)j * HH + ks * 256 + 128 + lane * 4]);
        Wr[jj][0] = v0.x; Wr[jj][1] = v0.y; Wr[jj][2] = v0.z; Wr[jj][3] = v0.w;
        Wr[jj][4] = v1.x; Wr[jj][5] = v1.y; Wr[jj][6] = v1.z; Wr[jj][7] = v1.w;
    }

    const int nout = tid >> 3;   // 0..31
    const int jout = tid & 7;    // 0..7

    // ---- t = 0: h_0 = proj[:, 0]   (each CTA writes its 8 columns)
    {
        const size_t idx = ((size_t)nout * TT) * HH + j0 + jout;
        __stcg(&out[idx], __ldg(&proj[idx]));
    }
    grid_barrier(tid);

    for (int t = 1; t < TT; t++) {
#pragma unroll 8
        for (int n = 0; n < NB; n++) {
            const float* hrow = out + ((size_t)n * TT + (t - 1)) * HH + ks * 256;
            const float4 h0 = __ldcg(reinterpret_cast<const float4*>(hrow + lane * 4));
            const float4 h1 = __ldcg(reinterpret_cast<const float4*>(hrow + 128 + lane * 4));
            const float hv[8] = {h0.x, h0.y, h0.z, h0.w, h1.x, h1.y, h1.z, h1.w};
            float s0 = 0.f, s1 = 0.f, s2 = 0.f, s3 = 0.f;
#pragma unroll
            for (int i = 0; i < 8; i++) {
                s0 += hv[i] * Wr[0][i];
                s1 += hv[i] * Wr[1][i];
                s2 += hv[i] * Wr[2][i];
                s3 += hv[i] * Wr[3][i];
            }
#pragma unroll
            for (int off = 16; off; off >>= 1) {
                s0 += __shfl_xor_sync(0xffffffffu, s0, off);
                s1 += __shfl_xor_sync(0xffffffffu, s1, off);
                s2 += __shfl_xor_sync(0xffffffffu, s2, off);
                s3 += __shfl_xor_sync(0xffffffffu, s3, off);
            }
            if (lane < 4) {
                const float v = (lane == 0) ? s0 : (lane == 1) ? s1
                              : (lane == 2) ? s2 : s3;
                partial[ks][n][jq * 4 + lane] = v;
            }
        }
        __syncthreads();

        // h_t[n, j] = sum_ks partial + proj[n, t-1, j]   (NOTE: t-1)
        const float sum = partial[0][nout][jout] + partial[1][nout][jout]
                        + partial[2][nout][jout] + partial[3][nout][jout];
        const float u = __ldg(&proj[((size_t)nout * TT + (t - 1)) * HH + j0 + jout]);
        __stcg(&out[((size_t)nout * TT + t) * HH + j0 + jout], sum + u);

        grid_barrier(tid);
    }
}

// =====================================================================
extern "C" void kernel_launch(void* const* d_in, const int* in_sizes, int n_in,
                              void* d_out, int out_size)
{
    // Map inputs by element count (robust to ordering).
    const float* x   = nullptr;
    const float* wih = nullptr;
    const float* bih = nullptr;
    const float* whh = nullptr;
    for (int i = 0; i < n_in; i++) {
        const long s = in_sizes[i];
        if      (s == (long)NB * TT * II) x   = (const float*)d_in[i];
        else if (s == (long)HH * II)      wih = (const float*)d_in[i];
        else if (s == (long)HH)           bih = (const float*)d_in[i];
        else if (s == (long)HH * HH)      whh = (const float*)d_in[i];
    }
    float* out = (float*)d_out;
    const size_t NTH = (size_t)NB * TT * HH;
    float* proj = out + NTH;    // second tuple slot doubles as proj scratch

    dim3 gridA(HH / 64, (NB * TT) / 128);   // x: n-tiles (fast), y: m-tiles
    proj_gemm<<<gridA, 256>>>(x, wih, bih, proj);

    recurrence<<<RBLOCKS, 256>>>(whh, proj, out);

    // Overwrite proj scratch with the duplicate output (tuple (out, out)).
    cudaMemcpyAsync(proj, out, NTH * sizeof(float),
                    cudaMemcpyDeviceToDevice, 0);
}

// round 10
// speedup vs baseline: 1.3635x; 1.3635x over previous
#include <cuda_runtime.h>
#include <cstdint>

#define NB 32
#define TT 2048
#define II 512
#define HH 1024

// =====================================================================
// Phase 1: proj = x @ w_ih^T + b_ih  -> written into out2 (second half
// of d_out, scratch until the final duplicate copy).
// =====================================================================
__global__ __launch_bounds__(256) void proj_gemm(
    const float* __restrict__ x,
    const float* __restrict__ wih,
    const float* __restrict__ bih,
    float* __restrict__ proj)
{
    __shared__ float As[16][132];
    __shared__ float Bs[16][68];

    const int tid = threadIdx.x;
    const int n0 = blockIdx.x * 64;
    const int m0 = blockIdx.y * 128;

    const int ar = tid >> 2;
    const int ac = (tid & 3) << 2;
    const int ty = tid >> 4;
    const int tx = tid & 15;

    float acc[8][4];
#pragma unroll
    for (int i = 0; i < 8; i++)
#pragma unroll
        for (int j = 0; j < 4; j++) acc[i][j] = 0.0f;

    for (int kk = 0; kk < II / 16; kk++) {
        const int k0 = kk * 16;
        const float4 a0 = *reinterpret_cast<const float4*>(
            &x[(size_t)(m0 + ar) * II + k0 + ac]);
        const float4 a1 = *reinterpret_cast<const float4*>(
            &x[(size_t)(m0 + 64 + ar) * II + k0 + ac]);
        const float4 b0 = *reinterpret_cast<const float4*>(
            &wih[(size_t)(n0 + ar) * II + k0 + ac]);

        __syncthreads();
        As[ac + 0][ar] = a0.x;  As[ac + 1][ar] = a0.y;
        As[ac + 2][ar] = a0.z;  As[ac + 3][ar] = a0.w;
        As[ac + 0][64 + ar] = a1.x;  As[ac + 1][64 + ar] = a1.y;
        As[ac + 2][64 + ar] = a1.z;  As[ac + 3][64 + ar] = a1.w;
        Bs[ac + 0][ar] = b0.x;  Bs[ac + 1][ar] = b0.y;
        Bs[ac + 2][ar] = b0.z;  Bs[ac + 3][ar] = b0.w;
        __syncthreads();

#pragma unroll
        for (int k = 0; k < 16; k++) {
            const float4 av0 = *reinterpret_cast<const float4*>(&As[k][ty * 8]);
            const float4 av1 = *reinterpret_cast<const float4*>(&As[k][ty * 8 + 4]);
            const float4 bv  = *reinterpret_cast<const float4*>(&Bs[k][tx * 4]);
            float a[8] = {av0.x, av0.y, av0.z, av0.w, av1.x, av1.y, av1.z, av1.w};
            float b[4] = {bv.x, bv.y, bv.z, bv.w};
#pragma unroll
            for (int i = 0; i < 8; i++)
#pragma unroll
                for (int j = 0; j < 4; j++)
                    acc[i][j] += a[i] * b[j];
        }
    }

    const float4 bias = *reinterpret_cast<const float4*>(&bih[n0 + tx * 4]);
#pragma unroll
    for (int r = 0; r < 8; r++) {
        const int m = m0 + ty * 8 + r;
        float4 o;
        o.x = acc[r][0] + bias.x;
        o.y = acc[r][1] + bias.y;
        o.z = acc[r][2] + bias.z;
        o.w = acc[r][3] + bias.w;
        *reinterpret_cast<float4*>(&proj[(size_t)m * HH + n0 + tx * 4]) = o;
    }
}

// =====================================================================
// Phase 2: persistent recurrence, SHUFFLE-FREE.
//   h_t = h_{t-1} @ W^T + proj[:, t-1]
// h kept TRANSPOSED in ping-pong scratch g_ht[2][HH][32] ([k][n]) so the
// compute warp maps lane = n and accumulates 8 j-columns in registers.
// 128 CTAs x 256 thr; CTA owns 8 j. W slice lives in smem (broadcast
// reads). ht reads are __ldcg (L1 not coherent across SMs).
// =====================================================================
#define RBLOCKS 128

__device__ float g_ht[2][HH * 32];      // 256 KB transposed h ping-pong
__device__ unsigned g_count = 0;
__device__ unsigned g_phase = 0;

__device__ __forceinline__ void grid_barrier(int tid)
{
    __syncthreads();
    if (tid == 0) {
        volatile unsigned* vphase = &g_phase;
        const unsigned my = *vphase;      // read BEFORE arriving
        __threadfence();                  // publish writes (L2)
        const unsigned arrived = atomicAdd(&g_count, 1u);
        if (arrived == RBLOCKS - 1) {
            g_count = 0;
            __threadfence();
            *vphase = my + 1;             // release
        } else {
            while (*vphase == my) { }
            __threadfence();              // acquire
        }
    }
    __syncthreads();
}

__global__ __launch_bounds__(256) void recurrence(
    const float* __restrict__ whh,
    const float* __restrict__ proj,
    float* __restrict__ out)
{
    __shared__ float4 Wp[HH * 2];            // [k][j0..3],[k][j4..7]  32 KB
    __shared__ float  partial[8][32][9];     // [warp][n][j] padded     9 KB
    __shared__ float  rsum[32][9];           // [n][j] padded           1.2 KB

    const int tid  = threadIdx.x;
    const int w    = tid >> 5;     // warp 0..7 -> k-slice of 128
    const int lane = tid & 31;     // lane = n in compute loop
    const int j0   = blockIdx.x * 8;

    // Stage W slice: Wp[k*2+0] = W[j0..j0+3][k], Wp[k*2+1] = W[j0+4..7][k]
    for (int idx = tid; idx < HH * 2; idx += 256) {
        const int k  = idx >> 1;
        const int jh = (idx & 1) * 4;
        float4 v;
        v.x = whh[(size_t)(j0 + jh + 0) * HH + k];
        v.y = whh[(size_t)(j0 + jh + 1) * HH + k];
        v.z = whh[(size_t)(j0 + jh + 2) * HH + k];
        v.w = whh[(size_t)(j0 + jh + 3) * HH + k];
        Wp[idx] = v;
    }

    // ---- t = 0: h_0 = proj[:, 0]; write out AND transposed scratch
    {
        const int n = tid & 31;
        const int j = tid >> 5;          // 0..7
        const float v = __ldg(&proj[((size_t)n * TT) * HH + j0 + j]);
        out[((size_t)n * TT) * HH + j0 + j] = v;
        __stcg(&g_ht[0][(j0 + j) * 32 + n], v);
    }
    grid_barrier(tid);

    const int rn = tid & 31;     // reduce-phase n
    const int rj = tid >> 5;     // reduce-phase j (0..7)
    const int on = tid >> 3;     // out-store n (0..31)
    const int oj = tid & 7;      // out-store j (0..7)

    for (int t = 1; t < TT; t++) {
        const float* __restrict__ htp = g_ht[(t - 1) & 1];
        float* __restrict__       htn = g_ht[t & 1];

        float acc0 = 0.f, acc1 = 0.f, acc2 = 0.f, acc3 = 0.f;
        float acc4 = 0.f, acc5 = 0.f, acc6 = 0.f, acc7 = 0.f;

        const int k0 = w * 128;
#pragma unroll 16
        for (int kk = 0; kk < 128; kk++) {
            const int k = k0 + kk;
            const float hv = __ldcg(&htp[k * 32 + lane]);   // coalesced line
            const float4 wa = Wp[k * 2 + 0];                // broadcast
            const float4 wb = Wp[k * 2 + 1];
            acc0 += hv * wa.x;  acc1 += hv * wa.y;
            acc2 += hv * wa.z;  acc3 += hv * wa.w;
            acc4 += hv * wb.x;  acc5 += hv * wb.y;
            acc6 += hv * wb.z;  acc7 += hv * wb.w;
        }
        partial[w][lane][0] = acc0;  partial[w][lane][1] = acc1;
        partial[w][lane][2] = acc2;  partial[w][lane][3] = acc3;
        partial[w][lane][4] = acc4;  partial[w][lane][5] = acc5;
        partial[w][lane][6] = acc6;  partial[w][lane][7] = acc7;
        __syncthreads();

        // reduce 8 k-slices + add u = proj[:, t-1]
        {
            float s = partial[0][rn][rj] + partial[1][rn][rj]
                    + partial[2][rn][rj] + partial[3][rn][rj]
                    + partial[4][rn][rj] + partial[5][rn][rj]
                    + partial[6][rn][rj] + partial[7][rn][rj];
            s += __ldg(&proj[((size_t)rn * TT + (t - 1)) * HH + j0 + rj]);
            rsum[rn][rj] = s;
        }
        __syncthreads();

        // store h_t: transposed scratch (coalesced) + final out (sectors)
        __stcg(&htn[(j0 + rj) * 32 + rn], rsum[rn][rj]);
        out[((size_t)on * TT + t) * HH + j0 + oj] = rsum[on][oj];

        grid_barrier(tid);
    }
}

// =====================================================================
extern "C" void kernel_launch(void* const* d_in, const int* in_sizes, int n_in,
                              void* d_out, int out_size)
{
    const float* x   = nullptr;
    const float* wih = nullptr;
    const float* bih = nullptr;
    const float* whh = nullptr;
    for (int i = 0; i < n_in; i++) {
        const long s = in_sizes[i];
        if      (s == (long)NB * TT * II) x   = (const float*)d_in[i];
        else if (s == (long)HH * II)      wih = (const float*)d_in[i];
        else if (s == (long)HH)           bih = (const float*)d_in[i];
        else if (s == (long)HH * HH)      whh = (const float*)d_in[i];
    }
    float* out = (float*)d_out;
    const size_t NTH = (size_t)NB * TT * HH;
    float* proj = out + NTH;    // second tuple slot doubles as proj scratch

    dim3 gridA(HH / 64, (NB * TT) / 128);
    proj_gemm<<<gridA, 256>>>(x, wih, bih, proj);

    recurrence<<<RBLOCKS, 256>>>(whh, proj, out);

    // Overwrite proj scratch with the duplicate output (tuple (out, out)).
    cudaMemcpyAsync(proj, out, NTH * sizeof(float),
                    cudaMemcpyDeviceToDevice, 0);
}

// round 11
// speedup vs baseline: 2.6087x; 1.9133x over previous
#include <cuda_runtime.h>
#include <cstdint>

#define NB 32
#define TT 2048
#define II 512
#define HH 1024

// =====================================================================
// Phase 1: proj = x @ w_ih^T + b_ih  -> second half of d_out (scratch).
// =====================================================================
__global__ __launch_bounds__(256) void proj_gemm(
    const float* __restrict__ x,
    const float* __restrict__ wih,
    const float* __restrict__ bih,
    float* __restrict__ proj)
{
    __shared__ float As[16][132];
    __shared__ float Bs[16][68];

    const int tid = threadIdx.x;
    const int n0 = blockIdx.x * 64;
    const int m0 = blockIdx.y * 128;

    const int ar = tid >> 2;
    const int ac = (tid & 3) << 2;
    const int ty = tid >> 4;
    const int tx = tid & 15;

    float acc[8][4];
#pragma unroll
    for (int i = 0; i < 8; i++)
#pragma unroll
        for (int j = 0; j < 4; j++) acc[i][j] = 0.0f;

    for (int kk = 0; kk < II / 16; kk++) {
        const int k0 = kk * 16;
        const float4 a0 = *reinterpret_cast<const float4*>(
            &x[(size_t)(m0 + ar) * II + k0 + ac]);
        const float4 a1 = *reinterpret_cast<const float4*>(
            &x[(size_t)(m0 + 64 + ar) * II + k0 + ac]);
        const float4 b0 = *reinterpret_cast<const float4*>(
            &wih[(size_t)(n0 + ar) * II + k0 + ac]);

        __syncthreads();
        As[ac + 0][ar] = a0.x;  As[ac + 1][ar] = a0.y;
        As[ac + 2][ar] = a0.z;  As[ac + 3][ar] = a0.w;
        As[ac + 0][64 + ar] = a1.x;  As[ac + 1][64 + ar] = a1.y;
        As[ac + 2][64 + ar] = a1.z;  As[ac + 3][64 + ar] = a1.w;
        Bs[ac + 0][ar] = b0.x;  Bs[ac + 1][ar] = b0.y;
        Bs[ac + 2][ar] = b0.z;  Bs[ac + 3][ar] = b0.w;
        __syncthreads();

#pragma unroll
        for (int k = 0; k < 16; k++) {
            const float4 av0 = *reinterpret_cast<const float4*>(&As[k][ty * 8]);
            const float4 av1 = *reinterpret_cast<const float4*>(&As[k][ty * 8 + 4]);
            const float4 bv  = *reinterpret_cast<const float4*>(&Bs[k][tx * 4]);
            float a[8] = {av0.x, av0.y, av0.z, av0.w, av1.x, av1.y, av1.z, av1.w};
            float b[4] = {bv.x, bv.y, bv.z, bv.w};
#pragma unroll
            for (int i = 0; i < 8; i++)
#pragma unroll
                for (int j = 0; j < 4; j++)
                    acc[i][j] += a[i] * b[j];
        }
    }

    const float4 bias = *reinterpret_cast<const float4*>(&bih[n0 + tx * 4]);
#pragma unroll
    for (int r = 0; r < 8; r++) {
        const int m = m0 + ty * 8 + r;
        float4 o;
        o.x = acc[r][0] + bias.x;
        o.y = acc[r][1] + bias.y;
        o.z = acc[r][2] + bias.z;
        o.w = acc[r][3] + bias.w;
        *reinterpret_cast<float4*>(&proj[(size_t)m * HH + n0 + tx * 4]) = o;
    }
}

// =====================================================================
// Phase 2: persistent recurrence.  h_t = h_{t-1} @ W^T + proj[:, t-1]
// 512 threads, 16 warps; warp w owns a 64-wide k slice; lane = n.
// FFMA2 (fma.rn.f32x2) packs the 8 j-accumulators into 4 b64 regs.
// h kept transposed ([k][n]) in ping-pong scratch; __ldcg for cross-SM
// coherence. Rotated smem columns -> zero bank conflicts, no padding.
// smem: Wp 32KB + partial 16KB = 48KB exactly (1 CTA/SM).
// =====================================================================
#define RBLOCKS 128

__device__ float g_ht[2][HH * 32];      // 256 KB transposed h ping-pong
__device__ unsigned g_count = 0;
__device__ unsigned g_phase = 0;

__device__ __forceinline__ void grid_barrier(int tid)
{
    __syncthreads();
    if (tid == 0) {
        volatile unsigned* vphase = &g_phase;
        const unsigned my = *vphase;      // read BEFORE arriving
        __threadfence();                  // publish writes (L2)
        const unsigned arrived = atomicAdd(&g_count, 1u);
        if (arrived == RBLOCKS - 1) {
            g_count = 0;
            __threadfence();
            *vphase = my + 1;             // release
        } else {
            while (*vphase == my) { }
            __threadfence();              // acquire
        }
    }
    __syncthreads();
}

__global__ __launch_bounds__(512) void recurrence(
    const float* __restrict__ whh,
    const float* __restrict__ proj,
    float* __restrict__ out)
{
    __shared__ float4 Wp[HH * 2];            // [k]{j0..3},{j4..7}  32 KB
    __shared__ float  partial[16][8][32];    // [slice][j][rot(n)]  16 KB

    const int tid  = threadIdx.x;
    const int w    = tid >> 5;     // warp 0..15 -> 64-wide k slice
    const int lane = tid & 31;     // lane = n
    const int j0   = blockIdx.x * 8;

    // Stage W slice: Wp[k*2+0] = W[j0..3][k], Wp[k*2+1] = W[j4..7][k]
    for (int idx = tid; idx < HH * 2; idx += 512) {
        const int k  = idx >> 1;
        const int jh = (idx & 1) * 4;
        float4 v;
        v.x = whh[(size_t)(j0 + jh + 0) * HH + k];
        v.y = whh[(size_t)(j0 + jh + 1) * HH + k];
        v.z = whh[(size_t)(j0 + jh + 2) * HH + k];
        v.w = whh[(size_t)(j0 + jh + 3) * HH + k];
        Wp[idx] = v;
    }

    // ---- t = 0: h_0 = proj[:, 0]
    if (tid < 256) {
        const int n = tid & 31;
        const int j = tid >> 5;
        const float v = __ldg(&proj[((size_t)n * TT) * HH + j0 + j]);
        out[((size_t)n * TT) * HH + j0 + j] = v;
        __stcg(&g_ht[0][(j0 + j) * 32 + n], v);
    }
    grid_barrier(tid);

    // Reduce-phase roles: tid<256 -> store out (n=tid>>3, j=tid&7),
    //                     tid>=256 -> store transposed ht (n=tid&31, j=tid>>5)
    const bool role_out = (tid < 256);
    const int tid2 = tid & 255;
    const int rn = role_out ? (tid2 >> 3) : (tid2 & 31);
    const int rj = role_out ? (tid2 & 7)  : (tid2 >> 5);

    const int k0 = w * 64;

    for (int t = 1; t < TT; t++) {
        const float* __restrict__ htp = g_ht[(t - 1) & 1];
        float* __restrict__       htn = g_ht[t & 1];

        // Prefetch proj term for the reduce phase.
        const float pu = __ldg(&proj[((size_t)rn * TT + (t - 1)) * HH + j0 + rj]);

        unsigned long long acc01 = 0ull, acc23 = 0ull, acc45 = 0ull, acc67 = 0ull;

        float hb0[8], hb1[8];
#pragma unroll
        for (int i = 0; i < 8; i++)
            hb0[i] = __ldcg(&htp[(k0 + i) * 32 + lane]);

#pragma unroll
        for (int kb = 0; kb < 64; kb += 8) {
            float* cur = ((kb >> 3) & 1) ? hb1 : hb0;
            float* nxt = ((kb >> 3) & 1) ? hb0 : hb1;
            if (kb + 8 < 64) {
#pragma unroll
                for (int i = 0; i < 8; i++)
                    nxt[i] = __ldcg(&htp[(k0 + kb + 8 + i) * 32 + lane]);
            }
#pragma unroll
            for (int i = 0; i < 8; i++) {
                const int k = k0 + kb + i;
                unsigned long long hh2;
                const unsigned hu = __float_as_uint(cur[i]);
                asm("mov.b64 %0, {%1, %1};" : "=l"(hh2) : "r"(hu));
                const ulonglong2 wA = *reinterpret_cast<const ulonglong2*>(&Wp[k * 2 + 0]);
                const ulonglong2 wB = *reinterpret_cast<const ulonglong2*>(&Wp[k * 2 + 1]);
                asm("fma.rn.f32x2 %0, %1, %2, %0;" : "+l"(acc01) : "l"(hh2), "l"(wA.x));
                asm("fma.rn.f32x2 %0, %1, %2, %0;" : "+l"(acc23) : "l"(hh2), "l"(wA.y));
                asm("fma.rn.f32x2 %0, %1, %2, %0;" : "+l"(acc45) : "l"(hh2), "l"(wB.x));
                asm("fma.rn.f32x2 %0, %1, %2, %0;" : "+l"(acc67) : "l"(hh2), "l"(wB.y));
            }
        }

        // Unpack accumulators -> partial, rotated columns (conflict-free).
        {
            unsigned lo, hi;
            asm("mov.b64 {%0,%1}, %2;" : "=r"(lo), "=r"(hi) : "l"(acc01));
            partial[w][0][(lane +  0) & 31] = __uint_as_float(lo);
            partial[w][1][(lane +  4) & 31] = __uint_as_float(hi);
            asm("mov.b64 {%0,%1}, %2;" : "=r"(lo), "=r"(hi) : "l"(acc23));
            partial[w][2][(lane +  8) & 31] = __uint_as_float(lo);
            partial[w][3][(lane + 12) & 31] = __uint_as_float(hi);
            asm("mov.b64 {%0,%1}, %2;" : "=r"(lo), "=r"(hi) : "l"(acc45));
            partial[w][4][(lane + 16) & 31] = __uint_as_float(lo);
            partial[w][5][(lane + 20) & 31] = __uint_as_float(hi);
            asm("mov.b64 {%0,%1}, %2;" : "=r"(lo), "=r"(hi) : "l"(acc67));
            partial[w][6][(lane + 24) & 31] = __uint_as_float(lo);
            partial[w][7][(lane + 28) & 31] = __uint_as_float(hi);
        }
        __syncthreads();

        // Every thread reduces its own (rn, rj): 16 slices + proj term.
        float s = pu;
#pragma unroll
        for (int sl = 0; sl < 16; sl++)
            s += partial[sl][rj][(rn + 4 * rj) & 31];

        if (role_out) {
            out[((size_t)rn * TT + t) * HH + j0 + rj] = s;      // 32B sectors
        } else {
            __stcg(&htn[(j0 + rj) * 32 + rn], s);               // coalesced
        }

        grid_barrier(tid);
    }
}

// =====================================================================
extern "C" void kernel_launch(void* const* d_in, const int* in_sizes, int n_in,
                              void* d_out, int out_size)
{
    const float* x   = nullptr;
    const float* wih = nullptr;
    const float* bih = nullptr;
    const float* whh = nullptr;
    for (int i = 0; i < n_in; i++) {
        const long s = in_sizes[i];
        if      (s == (long)NB * TT * II) x   = (const float*)d_in[i];
        else if (s == (long)HH * II)      wih = (const float*)d_in[i];
        else if (s == (long)HH)           bih = (const float*)d_in[i];
        else if (s == (long)HH * HH)      whh = (const float*)d_in[i];
    }
    float* out = (float*)d_out;
    const size_t NTH = (size_t)NB * TT * HH;
    float* proj = out + NTH;    // second tuple slot doubles as proj scratch

    dim3 gridA(HH / 64, (NB * TT) / 128);
    proj_gemm<<<gridA, 256>>>(x, wih, bih, proj);

    recurrence<<<RBLOCKS, 512>>>(whh, proj, out);

    // Overwrite proj scratch with the duplicate output (tuple (out, out)).
    cudaMemcpyAsync(proj, out, NTH * sizeof(float),
                    cudaMemcpyDeviceToDevice, 0);
}